// round 1
// baseline (speedup 1.0000x reference)
#include <cuda_runtime.h>

// VectorQuantizer: z_e [32,64,64,64] f32, codebook [512,64] f32.
// row n (n = b*4096 + h*64 + w) reads z_e[b, :, h, w] (stride 4096),
// argmin_k ( ||z||^2 + ||e_k||^2 - 2 z.e_k ), output codebook row contiguous.

#define N_ROWS   131072
#define K_CODES  512
#define D_DIM    64
#define ZQ_ELEMS (N_ROWS * D_DIM)   // 8388608

__device__ int g_idx[N_ROWS];

__device__ __forceinline__ unsigned long long pack_dup(float x) {
    unsigned long long r;
    asm("mov.b64 %0, {%1, %1};" : "=l"(r) : "f"(x));
    return r;
}
__device__ __forceinline__ void fma2(unsigned long long &acc,
                                     unsigned long long a,
                                     unsigned long long b) {
    // packed fp32x2 FMA: acc.lo += a.lo*b.lo ; acc.hi += a.hi*b.hi
    asm("fma.rn.f32x2 %0, %1, %2, %3;" : "=l"(acc) : "l"(a), "l"(b), "l"(acc));
}
__device__ __forceinline__ void unpack2(unsigned long long v, float &lo, float &hi) {
    asm("mov.b64 {%0, %1}, %2;" : "=f"(lo), "=f"(hi) : "l"(v));
}

extern __shared__ float sh[];  // [32768] codebook pairs + [512] norms

// Pair layout: sh[kp*128 + d*2 + j] = cb[(2*kp + j)*64 + d]
// -> one 16B LDS loads (e_{2kp}[d], e_{2kp+1}[d], e_{2kp}[d+1], e_{2kp+1}[d+1])

__global__ void __launch_bounds__(256, 1)
vq_main(const float* __restrict__ z_e, const float* __restrict__ cb,
        float* __restrict__ fidx_out) {
    const int tid = threadIdx.x;

    // --- stage codebook into pair layout (coalesced gmem read) ---
    for (int i = tid; i < K_CODES * D_DIM; i += 256) {
        int k = i >> 6, d = i & 63;
        sh[(k >> 1) * 128 + d * 2 + (k & 1)] = cb[i];
    }
    __syncthreads();

    // --- code norms, sequential-d fp32 (mimic jnp.sum(codebook**2, axis=1)) ---
    float* norms = sh + K_CODES * D_DIM;
    for (int k = tid; k < K_CODES; k += 256) {
        const int base = (k >> 1) * 128 + (k & 1);
        float s = 0.0f;
#pragma unroll 8
        for (int d = 0; d < D_DIM; d++) {
            float v = sh[base + d * 2];
            s = __fadd_rn(s, __fmul_rn(v, v));
        }
        norms[k] = s;
    }
    __syncthreads();

    // --- load this thread's z row: strided gmem, coalesced across warp ---
    const int row  = blockIdx.x * 256 + tid;
    const int b    = row >> 12;
    const long base = (long)b * 262144 + (row & 4095);

    unsigned long long z2[D_DIM];
    float zn = 0.0f;
#pragma unroll
    for (int d = 0; d < D_DIM; d++) {
        float v = z_e[base + (long)d * 4096];
        zn = __fadd_rn(zn, __fmul_rn(v, v));   // ||z||^2, sequential order
        z2[d] = pack_dup(v);
    }

    // --- main loop: 256 code-pairs, packed f32x2 FMAs ---
    float best = 3.4e38f;
    int bestk = 0;
#pragma unroll 1
    for (int kp = 0; kp < K_CODES / 2; kp++) {
        const double2* ep = reinterpret_cast<const double2*>(sh + kp * 128);
        unsigned long long a0 = 0ULL, a1 = 0ULL;   // bits of (0.f, 0.f)
#pragma unroll
        for (int dd = 0; dd < 32; dd++) {
            double2 e = ep[dd];                    // LDS.128, warp-broadcast
            fma2(a0, z2[2 * dd],     __double_as_longlong(e.x));
            fma2(a1, z2[2 * dd + 1], __double_as_longlong(e.y));
        }
        float l0, h0, l1, h1;
        unpack2(a0, l0, h0);
        unpack2(a1, l1, h1);
        float dot0 = __fadd_rn(l0, l1);
        float dot1 = __fadd_rn(h0, h1);
        // dist = fl( fl(zn + en_k) - fl(2*dot) ), matching the reference expr
        float s0 = __fadd_rn(__fadd_rn(zn, norms[2 * kp]),
                             __fmul_rn(-2.0f, dot0));
        float s1 = __fadd_rn(__fadd_rn(zn, norms[2 * kp + 1]),
                             __fmul_rn(-2.0f, dot1));
        if (s0 < best) { best = s0; bestk = 2 * kp; }       // strict <: first-min,
        if (s1 < best) { best = s1; bestk = 2 * kp + 1; }   // matches jnp.argmin
    }

    g_idx[row] = bestk;
    if (fidx_out) fidx_out[row] = (float)bestk;
}

// --- gather: out[n*64+d] = cb[idx[n]*64+d], fully coalesced via float4 ---
__global__ void vq_gather(const float4* __restrict__ cb4, float4* __restrict__ out4) {
    int g = blockIdx.x * 256 + threadIdx.x;   // 0 .. 2097151
    int n = g >> 4;
    int j = g & 15;
    out4[g] = cb4[(g_idx[n] << 4) + j];
}

extern "C" void kernel_launch(void* const* d_in, const int* in_sizes, int n_in,
                              void* d_out, int out_size) {
    const float* z_e = (const float*)d_in[0];
    const float* cb  = (const float*)d_in[1];
    // defensive: if input order is swapped, fix it by size
    if (n_in >= 2 && in_sizes[0] == K_CODES * D_DIM) {
        const float* t = z_e; z_e = cb; cb = t;
    }
    float* out = (float*)d_out;

    const int smem_bytes = (K_CODES * D_DIM + K_CODES) * sizeof(float); // 133120
    cudaFuncSetAttribute(vq_main, cudaFuncAttributeMaxDynamicSharedMemorySize,
                         smem_bytes);

    // indices appended to output (as float) if the harness sized it that way
    float* fidx = (out_size > ZQ_ELEMS) ? out + ZQ_ELEMS : nullptr;

    vq_main<<<N_ROWS / 256, 256, smem_bytes>>>(z_e, cb, fidx);
    vq_gather<<<ZQ_ELEMS / 4 / 256, 256>>>((const float4*)cb, (float4*)out);
}

// round 2
// speedup vs baseline: 1.5404x; 1.5404x over previous
#include <cuda_runtime.h>

// VectorQuantizer: z_e [32,64,64,64] f32, codebook [512,64] f32.
// row n (n = b*4096 + h*64 + w) reads z_e[b, :, h, w] (stride 4096),
// argmin_k ( ||z||^2 + ||e_k||^2 - 2 z.e_k ), output codebook row contiguous.
//
// R2: d-pair f32x2 packing (no lane duplication -> half the z registers),
// 2 rows per thread (each codebook LDS.128 feeds 4 FFMA2), row-major smem codebook.

#define N_ROWS   131072
#define K_CODES  512
#define D_DIM    64
#define ZQ_ELEMS (N_ROWS * D_DIM)   // 8388608
#define ROWS_PER_CTA 512            // 256 threads x 2 rows

__device__ int g_idx[N_ROWS];

__device__ __forceinline__ unsigned long long pack2(float lo, float hi) {
    unsigned long long r;
    asm("mov.b64 %0, {%1, %2};" : "=l"(r) : "f"(lo), "f"(hi));
    return r;
}
__device__ __forceinline__ void fma2(unsigned long long &acc,
                                     unsigned long long a,
                                     unsigned long long b) {
    // packed fp32x2 FMA: acc.lo += a.lo*b.lo ; acc.hi += a.hi*b.hi
    asm("fma.rn.f32x2 %0, %1, %2, %3;" : "=l"(acc) : "l"(a), "l"(b), "l"(acc));
}
__device__ __forceinline__ void unpack2(unsigned long long v, float &lo, float &hi) {
    asm("mov.b64 {%0, %1}, %2;" : "=f"(lo), "=f"(hi) : "l"(v));
}

extern __shared__ float sh[];  // [32768] codebook row-major + [512] norms

__global__ void __launch_bounds__(256, 1)
vq_main(const float* __restrict__ z_e, const float* __restrict__ cb,
        float* __restrict__ fidx_out) {
    const int tid = threadIdx.x;

    // --- stage codebook row-major into smem (vectorized, coalesced) ---
    {
        const float4* src = reinterpret_cast<const float4*>(cb);
        float4* dst = reinterpret_cast<float4*>(sh);
#pragma unroll
        for (int i = 0; i < (K_CODES * D_DIM / 4) / 256; i++)
            dst[i * 256 + tid] = src[i * 256 + tid];
    }
    __syncthreads();

    // --- code norms, sequential-d fp32 ---
    float* norms = sh + K_CODES * D_DIM;
    for (int k = tid; k < K_CODES; k += 256) {
        const float* e = sh + k * D_DIM;
        float s = 0.0f;
#pragma unroll 8
        for (int d = 0; d < D_DIM; d++)
            s = __fadd_rn(s, __fmul_rn(e[d], e[d]));
        norms[k] = s;
    }
    __syncthreads();

    // --- this thread's two rows (warp-coalesced gmem reads) ---
    const int rowA = blockIdx.x * ROWS_PER_CTA + tid;
    const int rowB = rowA + 256;

    unsigned long long zA[D_DIM / 2], zB[D_DIM / 2];
    float znA = 0.0f, znB = 0.0f;
    {
        const long baseA = (long)(rowA >> 12) * 262144 + (rowA & 4095);
        const long baseB = (long)(rowB >> 12) * 262144 + (rowB & 4095);
#pragma unroll
        for (int j = 0; j < D_DIM / 2; j++) {
            float a0 = z_e[baseA + (long)(2 * j)     * 4096];
            float a1 = z_e[baseA + (long)(2 * j + 1) * 4096];
            znA = __fadd_rn(znA, __fmul_rn(a0, a0));
            znA = __fadd_rn(znA, __fmul_rn(a1, a1));
            zA[j] = pack2(a0, a1);
            float b0 = z_e[baseB + (long)(2 * j)     * 4096];
            float b1 = z_e[baseB + (long)(2 * j + 1) * 4096];
            znB = __fadd_rn(znB, __fmul_rn(b0, b0));
            znB = __fadd_rn(znB, __fmul_rn(b1, b1));
            zB[j] = pack2(b0, b1);
        }
    }

    // --- main loop: 256 code-pairs; 32 LDS.128 + 128 FFMA2 per iter ---
    float bestA = 3.4e38f, bestB = 3.4e38f;
    int bkA = 0, bkB = 0;
#pragma unroll 1
    for (int kp = 0; kp < K_CODES / 2; kp++) {
        const double2* e0p = reinterpret_cast<const double2*>(sh + (2 * kp) * D_DIM);
        const double2* e1p = e0p + (D_DIM / 4);     // next code row
        unsigned long long aA0 = 0ULL, aA1 = 0ULL;  // row A vs codes 2kp, 2kp+1
        unsigned long long aB0 = 0ULL, aB1 = 0ULL;  // row B vs codes 2kp, 2kp+1
#pragma unroll
        for (int dd = 0; dd < D_DIM / 4; dd++) {    // 16 iters, 2 d-pairs each
            double2 e0 = e0p[dd];                   // code 2kp,  dims 4dd..4dd+3
            double2 e1 = e1p[dd];                   // code 2kp+1
            unsigned long long za0 = zA[2 * dd], za1 = zA[2 * dd + 1];
            unsigned long long zb0 = zB[2 * dd], zb1 = zB[2 * dd + 1];
            fma2(aA0, za0, __double_as_longlong(e0.x));
            fma2(aA1, za0, __double_as_longlong(e1.x));
            fma2(aB0, zb0, __double_as_longlong(e0.x));
            fma2(aB1, zb0, __double_as_longlong(e1.x));
            fma2(aA0, za1, __double_as_longlong(e0.y));
            fma2(aA1, za1, __double_as_longlong(e1.y));
            fma2(aB0, zb1, __double_as_longlong(e0.y));
            fma2(aB1, zb1, __double_as_longlong(e1.y));
        }
        float n0 = norms[2 * kp], n1 = norms[2 * kp + 1];
        float lo, hi, dot, s;

        unpack2(aA0, lo, hi); dot = __fadd_rn(lo, hi);
        s = __fadd_rn(__fadd_rn(znA, n0), __fmul_rn(-2.0f, dot));
        if (s < bestA) { bestA = s; bkA = 2 * kp; }
        unpack2(aA1, lo, hi); dot = __fadd_rn(lo, hi);
        s = __fadd_rn(__fadd_rn(znA, n1), __fmul_rn(-2.0f, dot));
        if (s < bestA) { bestA = s; bkA = 2 * kp + 1; }

        unpack2(aB0, lo, hi); dot = __fadd_rn(lo, hi);
        s = __fadd_rn(__fadd_rn(znB, n0), __fmul_rn(-2.0f, dot));
        if (s < bestB) { bestB = s; bkB = 2 * kp; }
        unpack2(aB1, lo, hi); dot = __fadd_rn(lo, hi);
        s = __fadd_rn(__fadd_rn(znB, n1), __fmul_rn(-2.0f, dot));
        if (s < bestB) { bestB = s; bkB = 2 * kp + 1; }
    }

    g_idx[rowA] = bkA;
    g_idx[rowB] = bkB;
    if (fidx_out) {
        fidx_out[rowA] = (float)bkA;
        fidx_out[rowB] = (float)bkB;
    }
}

// --- gather: out[n*64+d] = cb[idx[n]*64+d], fully coalesced via float4 ---
__global__ void vq_gather(const float4* __restrict__ cb4, float4* __restrict__ out4) {
    int g = blockIdx.x * 256 + threadIdx.x;   // 0 .. 2097151
    int n = g >> 4;
    int j = g & 15;
    out4[g] = cb4[(g_idx[n] << 4) + j];
}

extern "C" void kernel_launch(void* const* d_in, const int* in_sizes, int n_in,
                              void* d_out, int out_size) {
    const float* z_e = (const float*)d_in[0];
    const float* cb  = (const float*)d_in[1];
    if (n_in >= 2 && in_sizes[0] == K_CODES * D_DIM) {  // defensive swap
        const float* t = z_e; z_e = cb; cb = t;
    }
    float* out = (float*)d_out;

    const int smem_bytes = (K_CODES * D_DIM + K_CODES) * sizeof(float); // 133120
    cudaFuncSetAttribute(vq_main, cudaFuncAttributeMaxDynamicSharedMemorySize,
                         smem_bytes);

    float* fidx = (out_size > ZQ_ELEMS) ? out + ZQ_ELEMS : nullptr;

    vq_main<<<N_ROWS / ROWS_PER_CTA, 256, smem_bytes>>>(z_e, cb, fidx);
    vq_gather<<<ZQ_ELEMS / 4 / 256, 256>>>((const float4*)cb, (float4*)out);
}